// round 2
// baseline (speedup 1.0000x reference)
#include <cuda_runtime.h>
#include <math.h>
#include <stdint.h>

// ---------------------------------------------------------------------------
// BagAttentionNet forward, fp32 SIMT baseline.
//   x(2048,64,512) -> relu(512->256) -> relu(256->256) -> relu(256->128) = h3
//   h3 -> sigmoid(128->128) -> sigmoid(128->64) -> dot(64->1) = d
//   per bag: gumbel softmax over C=64, keep top-20 (drop 44 smallest, stable),
//            re-softmax kept values -> w ; out = (w . h3) . E + eb
//   output = [ flatten(w) (131072 floats) | flatten(out) (2048 floats) ]
// ---------------------------------------------------------------------------

#define NB 2048
#define CI 64
#define MR (NB * CI)          // 131072
#define TAU_F 0.95f

// scratch (allocation-free rule: __device__ globals)
__device__ float g_h1[MR * 256];
__device__ float g_h2[MR * 256];
__device__ float g_h3[MR * 128];
__device__ float g_d1[MR * 128];
__device__ float g_d2[MR * 64];
__device__ float g_dd[MR];

__device__ __forceinline__ float act_apply(float v, int ACT) {
    if (ACT == 1) return v > 0.f ? v : 0.f;
    if (ACT == 2) return 1.f / (1.f + expf(-v));
    return v;
}

// C = act(A @ W + bias);  A: MxK row-major, W: KxN row-major, C: MxN.
// Requires M % BM == 0, N % BN == 0, K % BK == 0 (all true for this net).
template<int BM, int BN, int BK, int ACT>
__global__ void __launch_bounds__((BM / 8) * (BN / 8))
gemm_bias_act(const float* __restrict__ A, const float* __restrict__ W,
              const float* __restrict__ bias, float* __restrict__ Cmat,
              int K, int N)
{
    constexpr int TM = 8, TN = 8;
    constexpr int RX = BN / TN, RY = BM / TM, THREADS = RX * RY;
    constexpr int AK4 = BK / 4, WN4 = BN / 4;
    constexpr int AITERS = (BM * AK4) / THREADS;
    constexpr int WITERS = (BK * WN4) / THREADS;

    __shared__ float As[BK][BM + 4];
    __shared__ float Ws[BK][BN];

    const int tid  = threadIdx.x;
    const int tcol = tid % RX;
    const int trow = tid / RX;
    const int brow = blockIdx.y * BM;
    const int bcol = blockIdx.x * BN;
    const float* Ab = A + (size_t)brow * K;

    float acc[TM][TN];
#pragma unroll
    for (int i = 0; i < TM; i++)
#pragma unroll
        for (int j = 0; j < TN; j++) acc[i][j] = 0.f;

    for (int k0 = 0; k0 < K; k0 += BK) {
#pragma unroll
        for (int it = 0; it < AITERS; it++) {
            int t = tid + it * THREADS;
            int row = t / AK4, kv = t % AK4;
            float4 v = *(const float4*)(Ab + (size_t)row * K + k0 + kv * 4);
            As[kv * 4 + 0][row] = v.x;
            As[kv * 4 + 1][row] = v.y;
            As[kv * 4 + 2][row] = v.z;
            As[kv * 4 + 3][row] = v.w;
        }
#pragma unroll
        for (int it = 0; it < WITERS; it++) {
            int t = tid + it * THREADS;
            int row = t / WN4, cv = t % WN4;
            *(float4*)&Ws[row][cv * 4] =
                *(const float4*)(W + (size_t)(k0 + row) * N + bcol + cv * 4);
        }
        __syncthreads();

#pragma unroll
        for (int k = 0; k < BK; k++) {
            float a[TM], w[TN];
            *(float4*)&a[0] = *(const float4*)&As[k][trow * 4];
            *(float4*)&a[4] = *(const float4*)&As[k][BM / 2 + trow * 4];
            *(float4*)&w[0] = *(const float4*)&Ws[k][tcol * 4];
            *(float4*)&w[4] = *(const float4*)&Ws[k][BN / 2 + tcol * 4];
#pragma unroll
            for (int i = 0; i < TM; i++)
#pragma unroll
                for (int j = 0; j < TN; j++)
                    acc[i][j] += a[i] * w[j];
        }
        __syncthreads();
    }

#pragma unroll
    for (int i = 0; i < TM; i++) {
        int row = brow + (i < 4 ? trow * 4 + i : BM / 2 + trow * 4 + (i - 4));
#pragma unroll
        for (int jh = 0; jh < 2; jh++) {
            int col = bcol + (jh ? BN / 2 + tcol * 4 : tcol * 4);
            float4 bv = *(const float4*)(bias + col);
            float4 o;
            o.x = act_apply(acc[i][jh * 4 + 0] + bv.x, ACT);
            o.y = act_apply(acc[i][jh * 4 + 1] + bv.y, ACT);
            o.z = act_apply(acc[i][jh * 4 + 2] + bv.z, ACT);
            o.w = act_apply(acc[i][jh * 4 + 3] + bv.w, ACT);
            *(float4*)(Cmat + (size_t)row * N + col) = o;
        }
    }
}

// d[r] = d2[r,:] . D3 + db3   (K = 64), one warp per row
__global__ void dot_kernel(const float* __restrict__ d2, const float* __restrict__ D3,
                           const float* __restrict__ db3, float* __restrict__ dd)
{
    int gw   = (blockIdx.x * blockDim.x + threadIdx.x) >> 5;
    int lane = threadIdx.x & 31;
    if (gw >= MR) return;
    const float* row = d2 + (size_t)gw * 64;
    float s = row[lane] * D3[lane] + row[lane + 32] * D3[lane + 32];
#pragma unroll
    for (int o = 16; o > 0; o >>= 1) s += __shfl_down_sync(0xffffffffu, s, o);
    if (lane == 0) dd[gw] = s + db3[0];
}

// Per-bag: gumbel softmax, top-20 keep (stable), re-softmax, aggregate, project.
__global__ void __launch_bounds__(128)
final_kernel(const float* __restrict__ dd, const float* __restrict__ m,
             const float* __restrict__ u, const float* __restrict__ h3,
             const float* __restrict__ E, const float* __restrict__ eb,
             float* __restrict__ out_w, float* __restrict__ out_s)
{
    const int bag = blockIdx.x;
    const int t   = threadIdx.x;   // 128 threads

    __shared__ float sm[64];
    __shared__ float wf[64];
    __shared__ float red[128];

    // z = (m*d + gumbel(u)) / tau
    float z = 0.f;
    if (t < 64) {
        float logit = m[bag * 64 + t] * dd[bag * 64 + t];
        float uu = u[bag * 64 + t];
        float g = -logf(-logf(uu));
        z = (logit + g) / TAU_F;
    }

    // softmax over 64
    red[t] = (t < 64) ? z : -INFINITY;
    __syncthreads();
#pragma unroll
    for (int s = 64; s >= 1; s >>= 1) {
        if (t < s) red[t] = fmaxf(red[t], red[t + s]);
        __syncthreads();
    }
    float zmax = red[0];
    __syncthreads();

    float e = (t < 64) ? expf(z - zmax) : 0.f;
    red[t] = e;
    __syncthreads();
#pragma unroll
    for (int s = 64; s >= 1; s >>= 1) {
        if (t < s) red[t] += red[t + s];
        __syncthreads();
    }
    float psum = red[0];
    __syncthreads();

    float p = e / psum;
    if (t < 64) sm[t] = p;
    __syncthreads();

    // stable ascending-sort rank; drop pos < 44 (i.e. keep top 20)
    int keep = 0;
    if (t < 64) {
        int pos = 0;
#pragma unroll 8
        for (int j = 0; j < 64; j++) {
            float o = sm[j];
            pos += (o < p) || (o == p && j < t);
        }
        keep = (pos >= 44);
    }

    // masked re-softmax of the kept probability values
    red[t] = (t < 64 && keep) ? p : -INFINITY;
    __syncthreads();
#pragma unroll
    for (int s = 64; s >= 1; s >>= 1) {
        if (t < s) red[t] = fmaxf(red[t], red[t + s]);
        __syncthreads();
    }
    float m2 = red[0];
    __syncthreads();

    float e2 = (t < 64 && keep) ? expf(p - m2) : 0.f;
    red[t] = e2;
    __syncthreads();
#pragma unroll
    for (int s = 64; s >= 1; s >>= 1) {
        if (t < s) red[t] += red[t + s];
        __syncthreads();
    }
    float s2 = red[0];
    __syncthreads();

    float wfin = (t < 64 && keep) ? (e2 / s2) : 0.f;
    if (t < 64) {
        wf[t] = wfin;
        out_w[bag * 64 + t] = wfin;
    }
    __syncthreads();

    // agg[d] = sum_c wf[c] * h3[bag, c, d];  val = agg[d] * E[d]; reduce; +eb
    const float* hb = h3 + (size_t)bag * 64 * 128;
    float agg = 0.f;
#pragma unroll 8
    for (int c = 0; c < 64; c++) agg += wf[c] * hb[c * 128 + t];
    red[t] = agg * E[t];
    __syncthreads();
#pragma unroll
    for (int s = 64; s >= 1; s >>= 1) {
        if (t < s) red[t] += red[t + s];
        __syncthreads();
    }
    if (t == 0) out_s[bag] = red[0] + eb[0];
}

extern "C" void kernel_launch(void* const* d_in, const int* in_sizes, int n_in,
                              void* d_out, int out_size)
{
    const float* x   = (const float*)d_in[0];
    const float* m   = (const float*)d_in[1];
    const float* u   = (const float*)d_in[2];
    const float* W1  = (const float*)d_in[3];
    const float* b1  = (const float*)d_in[4];
    const float* W2  = (const float*)d_in[5];
    const float* b2  = (const float*)d_in[6];
    const float* W3  = (const float*)d_in[7];
    const float* b3  = (const float*)d_in[8];
    const float* D1  = (const float*)d_in[9];
    const float* db1 = (const float*)d_in[10];
    const float* D2  = (const float*)d_in[11];
    const float* db2 = (const float*)d_in[12];
    const float* D3  = (const float*)d_in[13];
    const float* db3 = (const float*)d_in[14];
    const float* E   = (const float*)d_in[15];
    const float* eb  = (const float*)d_in[16];
    float* out = (float*)d_out;

    float *h1, *h2, *h3, *d1, *d2, *dd;
    cudaGetSymbolAddress((void**)&h1, g_h1);
    cudaGetSymbolAddress((void**)&h2, g_h2);
    cudaGetSymbolAddress((void**)&h3, g_h3);
    cudaGetSymbolAddress((void**)&d1, g_d1);
    cudaGetSymbolAddress((void**)&d2, g_d2);
    cudaGetSymbolAddress((void**)&dd, g_dd);

    // h1 = relu(x @ W1 + b1)             131072 x 512 x 256
    gemm_bias_act<128,128,16,1><<<dim3(256/128, MR/128), 256>>>(x,  W1, b1, h1, 512, 256);
    // h2 = relu(h1 @ W2 + b2)            131072 x 256 x 256
    gemm_bias_act<128,128,16,1><<<dim3(256/128, MR/128), 256>>>(h1, W2, b2, h2, 256, 256);
    // h3 = relu(h2 @ W3 + b3)            131072 x 256 x 128
    gemm_bias_act<128,128,16,1><<<dim3(128/128, MR/128), 256>>>(h2, W3, b3, h3, 256, 128);
    // d1 = sigmoid(h3 @ D1 + db1)        131072 x 128 x 128
    gemm_bias_act<128,128,16,2><<<dim3(128/128, MR/128), 256>>>(h3, D1, db1, d1, 128, 128);
    // d2 = sigmoid(d1 @ D2 + db2)        131072 x 128 x 64
    gemm_bias_act<128, 64,16,2><<<dim3( 64/ 64, MR/128), 128>>>(d1, D2, db2, d2, 128, 64);
    // dd = d2 @ D3 + db3
    dot_kernel<<<MR / 8, 256>>>(d2, D3, db3, dd);
    // w + out
    final_kernel<<<NB, 128>>>(dd, m, u, h3, E, eb, out, out + MR);
}

// round 3
// speedup vs baseline: 1.0980x; 1.0980x over previous
#include <cuda_runtime.h>
#include <math.h>
#include <stdint.h>

// ---------------------------------------------------------------------------
// BagAttentionNet forward, fp32 with packed f32x2 FMA (FFMA2) GEMM.
//   x(2048,64,512) -> relu(512->256) -> relu(256->256) -> relu(256->128) = h3
//   h3 -> sigmoid(128->128) -> sigmoid(128->64) -> dot(64->1) = d
//   per bag: gumbel softmax over C=64, keep top-20 (stable), re-softmax -> w
//   out = (w . h3) . E + eb ; output = [flatten(w) | flatten(out)]
// ---------------------------------------------------------------------------

#define NB 2048
#define CI 64
#define MR (NB * CI)          // 131072
#define TAU_F 0.95f

typedef unsigned long long ull;

// scratch (allocation-free rule: __device__ globals)
__device__ float g_h1[MR * 256];
__device__ float g_h2[MR * 256];
__device__ float g_h3[MR * 128];
__device__ float g_d1[MR * 128];
__device__ float g_d2[MR * 64];
__device__ float g_dd[MR];

__device__ __forceinline__ float act_apply(float v, int ACT) {
    if (ACT == 1) return v > 0.f ? v : 0.f;
    if (ACT == 2) return __fdividef(1.f, 1.f + __expf(-v));  // fast sigmoid
    return v;
}

// C = act(A @ W + bias);  A: MxK row-major, W: KxN row-major, C: MxN.
// Inner product uses packed fma.rn.f32x2 (FFMA2): bit-exact fp32 per lane,
// 2x lane rate on the fma pipe vs scalar FFMA (rt_SMSP 2 -> effective 1).
template<int BM, int BN, int BK, int ACT>
__global__ void __launch_bounds__((BM / 8) * (BN / 8))
gemm_bias_act(const float* __restrict__ A, const float* __restrict__ W,
              const float* __restrict__ bias, float* __restrict__ Cmat,
              int K, int N)
{
    constexpr int TM = 8, TN = 8;
    constexpr int RX = BN / TN, RY = BM / TM, THREADS = RX * RY;
    constexpr int AK4 = BK / 4, WN4 = BN / 4;
    constexpr int AITERS = (BM * AK4) / THREADS;
    constexpr int WITERS = (BK * WN4) / THREADS;

    __shared__ float As[BK][BM + 4];
    __shared__ float Ws[BK][BN];

    const int tid  = threadIdx.x;
    const int tcol = tid % RX;
    const int trow = tid / RX;
    const int brow = blockIdx.y * BM;
    const int bcol = blockIdx.x * BN;
    const float* Ab = A + (size_t)brow * K;

    // acc pairs: acc2[i][j] holds columns (2j, 2j+1) of the 8x8 tile,
    // with j in 0..1 -> cols tcol*4 + {0..3}, j in 2..3 -> BN/2 + tcol*4 + {0..3}
    ull acc2[TM][TN / 2];
#pragma unroll
    for (int i = 0; i < TM; i++)
#pragma unroll
        for (int j = 0; j < TN / 2; j++) acc2[i][j] = 0ull;   // {0.f, 0.f}

    for (int k0 = 0; k0 < K; k0 += BK) {
#pragma unroll
        for (int it = 0; it < AITERS; it++) {
            int t = tid + it * THREADS;
            int row = t / AK4, kv = t % AK4;
            float4 v = *(const float4*)(Ab + (size_t)row * K + k0 + kv * 4);
            As[kv * 4 + 0][row] = v.x;
            As[kv * 4 + 1][row] = v.y;
            As[kv * 4 + 2][row] = v.z;
            As[kv * 4 + 3][row] = v.w;
        }
#pragma unroll
        for (int it = 0; it < WITERS; it++) {
            int t = tid + it * THREADS;
            int row = t / WN4, cv = t % WN4;
            *(float4*)&Ws[row][cv * 4] =
                *(const float4*)(W + (size_t)(k0 + row) * N + bcol + cv * 4);
        }
        __syncthreads();

#pragma unroll
        for (int k = 0; k < BK; k++) {
            float a[TM];
            *(float4*)&a[0] = *(const float4*)&As[k][trow * 4];
            *(float4*)&a[4] = *(const float4*)&As[k][BM / 2 + trow * 4];
            // natural 64-bit pairs of W straight from smem (LDS.128)
            ulonglong2 wA = *(const ulonglong2*)&Ws[k][tcol * 4];
            ulonglong2 wB = *(const ulonglong2*)&Ws[k][BN / 2 + tcol * 4];
            ull wv0 = wA.x, wv1 = wA.y, wv2 = wB.x, wv3 = wB.y;
#pragma unroll
            for (int i = 0; i < TM; i++) {
                ull ab;
                asm("mov.b64 %0, {%1, %1};" : "=l"(ab) : "f"(a[i]));
                asm("fma.rn.f32x2 %0, %1, %2, %0;" : "+l"(acc2[i][0]) : "l"(ab), "l"(wv0));
                asm("fma.rn.f32x2 %0, %1, %2, %0;" : "+l"(acc2[i][1]) : "l"(ab), "l"(wv1));
                asm("fma.rn.f32x2 %0, %1, %2, %0;" : "+l"(acc2[i][2]) : "l"(ab), "l"(wv2));
                asm("fma.rn.f32x2 %0, %1, %2, %0;" : "+l"(acc2[i][3]) : "l"(ab), "l"(wv3));
            }
        }
        __syncthreads();
    }

#pragma unroll
    for (int i = 0; i < TM; i++) {
        int row = brow + (i < 4 ? trow * 4 + i : BM / 2 + trow * 4 + (i - 4));
#pragma unroll
        for (int jh = 0; jh < 2; jh++) {
            int col = bcol + (jh ? BN / 2 + tcol * 4 : tcol * 4);
            float4 bv = *(const float4*)(bias + col);
            float v0, v1, v2, v3;
            asm("mov.b64 {%0, %1}, %2;" : "=f"(v0), "=f"(v1) : "l"(acc2[i][jh * 2 + 0]));
            asm("mov.b64 {%0, %1}, %2;" : "=f"(v2), "=f"(v3) : "l"(acc2[i][jh * 2 + 1]));
            float4 o;
            o.x = act_apply(v0 + bv.x, ACT);
            o.y = act_apply(v1 + bv.y, ACT);
            o.z = act_apply(v2 + bv.z, ACT);
            o.w = act_apply(v3 + bv.w, ACT);
            *(float4*)(Cmat + (size_t)row * N + col) = o;
        }
    }
}

// d[r] = d2[r,:] . D3 + db3   (K = 64), one warp per row
__global__ void dot_kernel(const float* __restrict__ d2, const float* __restrict__ D3,
                           const float* __restrict__ db3, float* __restrict__ dd)
{
    int gw   = (blockIdx.x * blockDim.x + threadIdx.x) >> 5;
    int lane = threadIdx.x & 31;
    if (gw >= MR) return;
    const float* row = d2 + (size_t)gw * 64;
    float s = row[lane] * D3[lane] + row[lane + 32] * D3[lane + 32];
#pragma unroll
    for (int o = 16; o > 0; o >>= 1) s += __shfl_down_sync(0xffffffffu, s, o);
    if (lane == 0) dd[gw] = s + db3[0];
}

// Per-bag: gumbel softmax, top-20 keep (stable), re-softmax, aggregate, project.
// Uses precise expf/logf: this kernel determines the hard keep-selection.
__global__ void __launch_bounds__(128)
final_kernel(const float* __restrict__ dd, const float* __restrict__ m,
             const float* __restrict__ u, const float* __restrict__ h3,
             const float* __restrict__ E, const float* __restrict__ eb,
             float* __restrict__ out_w, float* __restrict__ out_s)
{
    const int bag = blockIdx.x;
    const int t   = threadIdx.x;   // 128 threads

    __shared__ float sm[64];
    __shared__ float wf[64];
    __shared__ float red[128];

    // z = (m*d + gumbel(u)) / tau
    float z = 0.f;
    if (t < 64) {
        float logit = m[bag * 64 + t] * dd[bag * 64 + t];
        float uu = u[bag * 64 + t];
        float g = -logf(-logf(uu));
        z = (logit + g) / TAU_F;
    }

    // softmax over 64
    red[t] = (t < 64) ? z : -INFINITY;
    __syncthreads();
#pragma unroll
    for (int s = 64; s >= 1; s >>= 1) {
        if (t < s) red[t] = fmaxf(red[t], red[t + s]);
        __syncthreads();
    }
    float zmax = red[0];
    __syncthreads();

    float e = (t < 64) ? expf(z - zmax) : 0.f;
    red[t] = e;
    __syncthreads();
#pragma unroll
    for (int s = 64; s >= 1; s >>= 1) {
        if (t < s) red[t] += red[t + s];
        __syncthreads();
    }
    float psum = red[0];
    __syncthreads();

    float p = e / psum;
    if (t < 64) sm[t] = p;
    __syncthreads();

    // stable ascending-sort rank; drop pos < 44 (i.e. keep top 20)
    int keep = 0;
    if (t < 64) {
        int pos = 0;
#pragma unroll 8
        for (int j = 0; j < 64; j++) {
            float o = sm[j];
            pos += (o < p) || (o == p && j < t);
        }
        keep = (pos >= 44);
    }

    // masked re-softmax of the kept probability values
    red[t] = (t < 64 && keep) ? p : -INFINITY;
    __syncthreads();
#pragma unroll
    for (int s = 64; s >= 1; s >>= 1) {
        if (t < s) red[t] = fmaxf(red[t], red[t + s]);
        __syncthreads();
    }
    float m2 = red[0];
    __syncthreads();

    float e2 = (t < 64 && keep) ? expf(p - m2) : 0.f;
    red[t] = e2;
    __syncthreads();
#pragma unroll
    for (int s = 64; s >= 1; s >>= 1) {
        if (t < s) red[t] += red[t + s];
        __syncthreads();
    }
    float s2 = red[0];
    __syncthreads();

    float wfin = (t < 64 && keep) ? (e2 / s2) : 0.f;
    if (t < 64) {
        wf[t] = wfin;
        out_w[bag * 64 + t] = wfin;
    }
    __syncthreads();

    // agg[d] = sum_c wf[c] * h3[bag, c, d];  val = agg[d] * E[d]; reduce; +eb
    const float* hb = h3 + (size_t)bag * 64 * 128;
    float agg = 0.f;
#pragma unroll 8
    for (int c = 0; c < 64; c++) agg += wf[c] * hb[c * 128 + t];
    red[t] = agg * E[t];
    __syncthreads();
#pragma unroll
    for (int s = 64; s >= 1; s >>= 1) {
        if (t < s) red[t] += red[t + s];
        __syncthreads();
    }
    if (t == 0) out_s[bag] = red[0] + eb[0];
}

extern "C" void kernel_launch(void* const* d_in, const int* in_sizes, int n_in,
                              void* d_out, int out_size)
{
    const float* x   = (const float*)d_in[0];
    const float* m   = (const float*)d_in[1];
    const float* u   = (const float*)d_in[2];
    const float* W1  = (const float*)d_in[3];
    const float* b1  = (const float*)d_in[4];
    const float* W2  = (const float*)d_in[5];
    const float* b2  = (const float*)d_in[6];
    const float* W3  = (const float*)d_in[7];
    const float* b3  = (const float*)d_in[8];
    const float* D1  = (const float*)d_in[9];
    const float* db1 = (const float*)d_in[10];
    const float* D2  = (const float*)d_in[11];
    const float* db2 = (const float*)d_in[12];
    const float* D3  = (const float*)d_in[13];
    const float* db3 = (const float*)d_in[14];
    const float* E   = (const float*)d_in[15];
    const float* eb  = (const float*)d_in[16];
    float* out = (float*)d_out;

    float *h1, *h2, *h3, *d1, *d2, *dd;
    cudaGetSymbolAddress((void**)&h1, g_h1);
    cudaGetSymbolAddress((void**)&h2, g_h2);
    cudaGetSymbolAddress((void**)&h3, g_h3);
    cudaGetSymbolAddress((void**)&d1, g_d1);
    cudaGetSymbolAddress((void**)&d2, g_d2);
    cudaGetSymbolAddress((void**)&dd, g_dd);

    // h1 = relu(x @ W1 + b1)             131072 x 512 x 256
    gemm_bias_act<128,128,32,1><<<dim3(256/128, MR/128), 256>>>(x,  W1, b1, h1, 512, 256);
    // h2 = relu(h1 @ W2 + b2)            131072 x 256 x 256
    gemm_bias_act<128,128,32,1><<<dim3(256/128, MR/128), 256>>>(h1, W2, b2, h2, 256, 256);
    // h3 = relu(h2 @ W3 + b3)            131072 x 256 x 128
    gemm_bias_act<128,128,32,1><<<dim3(128/128, MR/128), 256>>>(h2, W3, b3, h3, 256, 128);
    // d1 = sigmoid(h3 @ D1 + db1)        131072 x 128 x 128
    gemm_bias_act<128,128,32,2><<<dim3(128/128, MR/128), 256>>>(h3, D1, db1, d1, 128, 128);
    // d2 = sigmoid(d1 @ D2 + db2)        131072 x 128 x 64
    gemm_bias_act<128, 64,32,2><<<dim3( 64/ 64, MR/128), 128>>>(d1, D2, db2, d2, 128, 64);
    // dd = d2 @ D3 + db3
    dot_kernel<<<MR / 8, 256>>>(d2, D3, db3, dd);
    // w + out
    final_kernel<<<NB, 128>>>(dd, m, u, h3, E, eb, out, out + MR);
}